// round 11
// baseline (speedup 1.0000x reference)
#include <cuda_runtime.h>
#include <cstdint>

// Problem constants
constexpr int NN  = 50000;   // nodes
constexpr int NE  = 800000;  // edges
constexpr int ND  = 64;      // node dim
constexpr int ED  = 64;      // edge dim
constexpr int HID = 128;     // hidden

constexpr int NTILE_E = NE / 256;             // 3125 edge tiles (256 edges)
constexpr int NTILE_N = (NN + 255) / 256;     // 196 node tiles
constexpr int PGRID   = 444;                  // 3 CTAs x 148 SMs, persistent

// Scratch (device globals: allocation-free)
__device__ float g_PR[NN * HID];   // x @ eW1[64:128]   (fp32 exact)
__device__ float g_PC[NN * HID];   // x @ eW1[128:192]  (fp32 exact)
__device__ float g_PX[NN * HID];   // x @ nW1[0:64]     (fp32 exact)
__device__ float g_msg[NN * ED];   // scatter-add accumulator

// ---------------------------------------------------------------------------
// helpers
// ---------------------------------------------------------------------------
__device__ __forceinline__ uint32_t f32_to_tf32(float f) {
    uint32_t u;
    asm("cvt.rna.tf32.f32 %0, %1;" : "=r"(u) : "f"(f));
    return u;
}

__device__ __forceinline__ void mma_tf32(float d[4], const uint32_t a[4],
                                         const uint32_t b[2]) {
    asm volatile(
        "mma.sync.aligned.m16n8k8.row.col.f32.tf32.tf32.f32 "
        "{%0,%1,%2,%3}, {%4,%5,%6,%7}, {%8,%9}, {%0,%1,%2,%3};"
        : "+f"(d[0]), "+f"(d[1]), "+f"(d[2]), "+f"(d[3])
        : "r"(a[0]), "r"(a[1]), "r"(a[2]), "r"(a[3]), "r"(b[0]), "r"(b[1]));
}

// L2-only (no L1) vector loads for the gather tables
__device__ __forceinline__ float2 ldcg2(const float* p) {
    float2 v;
    asm volatile("ld.global.cg.v2.f32 {%0,%1}, [%2];"
                 : "=f"(v.x), "=f"(v.y) : "l"(p));
    return v;
}

// ---------------------------------------------------------------------------
__global__ void zero_msg_kernel() {
    int i = blockIdx.x * blockDim.x + threadIdx.x;
    reinterpret_cast<float4*>(g_msg)[i] = make_float4(0.f, 0.f, 0.f, 0.f);
}

// ---------------------------------------------------------------------------
// Precompute PR/PC (fp32 exact): GEMM [NN,64] @ [64,256]
// ---------------------------------------------------------------------------
__global__ void __launch_bounds__(256, 2) precompute_kernel(
    const float* __restrict__ x, const float* __restrict__ eW1)
{
    extern __shared__ float sm[];
    float* Xs = sm;               // [64][68]
    float* Ws = sm + 64 * 68;     // [64][256]

    const int n0 = blockIdx.x * 64;
    const int tid = threadIdx.x;

    for (int idx = tid; idx < 64 * 64; idx += 256) {
        int r = idx >> 6, c = idx & 63;
        int n = n0 + r;
        Xs[r * 68 + c] = (n < NN) ? x[n * 64 + c] : 0.f;
    }
    for (int idx = tid; idx < 64 * 256; idx += 256) {
        int k = idx >> 8, j = idx & 255;
        float v = (j < 128) ? eW1[(64 + k) * 128 + j]
                            : eW1[(128 + k) * 128 + (j - 128)];
        Ws[k * 256 + j] = v;
    }
    __syncthreads();

    const int tx = tid & 15;
    const int ty = tid >> 4;

    float acc[4][16];
    #pragma unroll
    for (int i = 0; i < 4; i++)
        #pragma unroll
        for (int j = 0; j < 16; j++) acc[i][j] = 0.f;

    #pragma unroll 4
    for (int k = 0; k < 64; k++) {
        float a[4];
        #pragma unroll
        for (int i = 0; i < 4; i++) a[i] = Xs[(ty * 4 + i) * 68 + k];
        const float4 b0 = *(const float4*)&Ws[k * 256 + tx * 16 + 0];
        const float4 b1 = *(const float4*)&Ws[k * 256 + tx * 16 + 4];
        const float4 b2 = *(const float4*)&Ws[k * 256 + tx * 16 + 8];
        const float4 b3 = *(const float4*)&Ws[k * 256 + tx * 16 + 12];
        float b[16] = {b0.x, b0.y, b0.z, b0.w, b1.x, b1.y, b1.z, b1.w,
                       b2.x, b2.y, b2.z, b2.w, b3.x, b3.y, b3.z, b3.w};
        #pragma unroll
        for (int i = 0; i < 4; i++)
            #pragma unroll
            for (int j = 0; j < 16; j++)
                acc[i][j] = fmaf(a[i], b[j], acc[i][j]);
    }

    float* dst = (tx < 8) ? g_PR : g_PC;
    int    cb  = (tx < 8) ? tx * 16 : (tx - 8) * 16;
    #pragma unroll
    for (int i = 0; i < 4; i++) {
        int n = n0 + ty * 4 + i;
        if (n >= NN) continue;
        #pragma unroll
        for (int j = 0; j < 16; j += 4) {
            float4 o = make_float4(acc[i][j], acc[i][j + 1],
                                   acc[i][j + 2], acc[i][j + 3]);
            *(float4*)&dst[n * 128 + cb + j] = o;
        }
    }
}

// ---------------------------------------------------------------------------
// Precompute PX (fp32 exact): PX = x @ nW1[0:64]   [NN,128]
// ---------------------------------------------------------------------------
__global__ void __launch_bounds__(256, 2) precompute_px_kernel(
    const float* __restrict__ x, const float* __restrict__ nW1)
{
    extern __shared__ float sm[];
    float* Xs = sm;               // [64][68]
    float* Ws = sm + 64 * 68;     // [64][128]

    const int n0 = blockIdx.x * 64;
    const int tid = threadIdx.x;

    for (int idx = tid; idx < 64 * 64; idx += 256) {
        int r = idx >> 6, c = idx & 63;
        int n = n0 + r;
        Xs[r * 68 + c] = (n < NN) ? x[n * 64 + c] : 0.f;
    }
    for (int idx = tid; idx < 64 * 128; idx += 256)
        Ws[idx] = nW1[idx];
    __syncthreads();

    const int tx = tid & 15;
    const int ty = tid >> 4;

    float acc[4][8];
    #pragma unroll
    for (int i = 0; i < 4; i++)
        #pragma unroll
        for (int j = 0; j < 8; j++) acc[i][j] = 0.f;

    #pragma unroll 4
    for (int k = 0; k < 64; k++) {
        float a[4];
        #pragma unroll
        for (int i = 0; i < 4; i++) a[i] = Xs[(ty * 4 + i) * 68 + k];
        const float4 b0 = *(const float4*)&Ws[k * 128 + tx * 8 + 0];
        const float4 b1 = *(const float4*)&Ws[k * 128 + tx * 8 + 4];
        float b[8] = {b0.x, b0.y, b0.z, b0.w, b1.x, b1.y, b1.z, b1.w};
        #pragma unroll
        for (int i = 0; i < 4; i++)
            #pragma unroll
            for (int j = 0; j < 8; j++)
                acc[i][j] = fmaf(a[i], b[j], acc[i][j]);
    }

    #pragma unroll
    for (int i = 0; i < 4; i++) {
        int n = n0 + ty * 4 + i;
        if (n >= NN) continue;
        *(float4*)&g_PX[n * 128 + tx * 8 + 0] =
            make_float4(acc[i][0], acc[i][1], acc[i][2], acc[i][3]);
        *(float4*)&g_PX[n * 128 + tx * 8 + 4] =
            make_float4(acc[i][4], acc[i][5], acc[i][6], acc[i][7]);
    }
}

// ---------------------------------------------------------------------------
// Smem layout for persistent mma kernels: weights + biases ONLY (68352 B)
//   -> 3 CTAs/SM, 24 warps/SM; main loops are barrier-free.
// ---------------------------------------------------------------------------
constexpr int S_B1  = 0;          // B1frag [pane=kk*16+nn][66]   8448 floats
constexpr int S_B2  = 8448;       // B2frag [pane=kk*8+nn][66]    8448 floats
constexpr int S_EB1 = 16896;      // bias1 [128]
constexpr int S_EB2 = 17024;      // bias2 [64]
constexpr int MMA_SMEM_BYTES = 17088 * 4;   // 68352

// ---------------------------------------------------------------------------
// Edge kernel — persistent, barrier-free main loop.
// 256 threads / 8 warps; tile = 256 edges; warp w owns rows [32w, 32w+32)
// (two m16 sub-tiles sharing every B-fragment load).
// A comes straight from gmem (__ldg, read-once, high-MLP unrolled batch).
// ---------------------------------------------------------------------------
__global__ void __launch_bounds__(256, 3) edge_kernel(
    const float* __restrict__ edge_attr,
    const int*   __restrict__ edge_index,   // [2][NE]
    const float* __restrict__ eW1,
    const float* __restrict__ eb1,
    const float* __restrict__ eW2,
    const float* __restrict__ eb2,
    float* __restrict__ out_edge)
{
    extern __shared__ float sm[];
    uint32_t* smu = reinterpret_cast<uint32_t*>(sm);

    const int tid  = threadIdx.x;
    const int lane = tid & 31;
    const int w    = tid >> 5;           // 0..7
    const int gr   = lane >> 2;
    const int ct   = lane & 3;
    const int s0   = ct >> 1;
    const int s1   = 2 + (ct >> 1);
    const int sel  = ct & 1;
    const int even = (ct & 1) == 0;
    const int qb   = 4 * (ct >> 1);
    const int rA0  = 32 * w + gr;        // sub-tile 0 rows: rA0, rA0+8
    const int rA1  = rA0 + 16;           // sub-tile 1 rows: rA1, rA1+8

    // ---- prologue: weight fragments + biases (once per CTA) ----
    for (int t = tid; t < 2048; t += 256) {
        int k = t >> 5, n4 = (t & 31) << 2;
        float4 v = *(const float4*)&eW1[k * 128 + n4];
        int pane = (k >> 3) * 16 + (n4 >> 3);
        int j    = (k >> 2) & 1;
        int ln0  = ((n4 & 7) << 2) | (k & 3);
        uint32_t* p = &smu[S_B1 + pane * 66 + j];
        p[(ln0 + 0)  * 2] = f32_to_tf32(v.x);
        p[(ln0 + 4)  * 2] = f32_to_tf32(v.y);
        p[(ln0 + 8)  * 2] = f32_to_tf32(v.z);
        p[(ln0 + 12) * 2] = f32_to_tf32(v.w);
    }
    for (int t = tid; t < 2048; t += 256) {
        int k = t >> 4, n4 = (t & 15) << 2;
        float4 v = *(const float4*)&eW2[k * 64 + n4];
        int pane = (k >> 3) * 8 + (n4 >> 3);
        int j    = (k >> 2) & 1;
        int ln0  = ((n4 & 7) << 2) | (k & 3);
        uint32_t* p = &smu[S_B2 + pane * 66 + j];
        p[(ln0 + 0)  * 2] = f32_to_tf32(v.x);
        p[(ln0 + 4)  * 2] = f32_to_tf32(v.y);
        p[(ln0 + 8)  * 2] = f32_to_tf32(v.z);
        p[(ln0 + 12) * 2] = f32_to_tf32(v.w);
    }
    if (tid < 128) sm[S_EB1 + tid] = eb1[tid];
    if (tid < 64)  sm[S_EB2 + tid] = eb2[tid];
    __syncthreads();   // the ONLY block barrier

    // ---- persistent tile loop (no barriers: A is warp-private via LDG) ----
    for (int tile = blockIdx.x; tile < NTILE_E; tile += PGRID) {
        const int e0 = tile * 256;

        const int re00 = __ldg(&edge_index[e0 + rA0]);
        const int re01 = __ldg(&edge_index[e0 + rA0 + 8]);
        const int re10 = __ldg(&edge_index[e0 + rA1]);
        const int re11 = __ldg(&edge_index[e0 + rA1 + 8]);
        const int ce00 = __ldg(&edge_index[NE + e0 + rA0]);
        const int ce01 = __ldg(&edge_index[NE + e0 + rA0 + 8]);
        const int ce10 = __ldg(&edge_index[NE + e0 + rA1]);
        const int ce11 = __ldg(&edge_index[NE + e0 + rA1 + 8]);

        // ---- layer-1 mma: A direct from gmem; B shared by both sub-tiles ----
        float acc0[16][4], acc1[16][4];
        #pragma unroll
        for (int nn = 0; nn < 16; nn++) {
            acc0[nn][0] = acc0[nn][1] = acc0[nn][2] = acc0[nn][3] = 0.f;
            acc1[nn][0] = acc1[nn][1] = acc1[nn][2] = acc1[nn][3] = 0.f;
        }
        #pragma unroll
        for (int kk = 0; kk < 8; kk++) {
            const int col = kk * 8 + ct;
            const float* p00 = edge_attr + (size_t)(e0 + rA0) * 64 + col;
            const float* p01 = edge_attr + (size_t)(e0 + rA0 + 8) * 64 + col;
            const float* p10 = edge_attr + (size_t)(e0 + rA1) * 64 + col;
            const float* p11 = edge_attr + (size_t)(e0 + rA1 + 8) * 64 + col;
            uint32_t a0[4], a1[4];
            a0[0] = __float_as_uint(__ldg(p00));
            a0[1] = __float_as_uint(__ldg(p01));
            a0[2] = __float_as_uint(__ldg(p00 + 4));
            a0[3] = __float_as_uint(__ldg(p01 + 4));
            a1[0] = __float_as_uint(__ldg(p10));
            a1[1] = __float_as_uint(__ldg(p11));
            a1[2] = __float_as_uint(__ldg(p10 + 4));
            a1[3] = __float_as_uint(__ldg(p11 + 4));
            #pragma unroll
            for (int nn = 0; nn < 16; nn++) {
                uint32_t b[2];
                const uint2 bv = *(const uint2*)&smu[S_B1 + (kk * 16 + nn) * 66 + lane * 2];
                b[0] = bv.x; b[1] = bv.y;
                mma_tf32(acc0[nn], a0, b);
                mma_tf32(acc1[nn], a1, b);
            }
        }

        // ---- epilogue: H = rna(relu(C1 + PR + PC + eb1)), gathers via .cg ----
        {
            const float* PR00 = g_PR + (size_t)re00 * 128;
            const float* PR01 = g_PR + (size_t)re01 * 128;
            const float* PC00 = g_PC + (size_t)ce00 * 128;
            const float* PC01 = g_PC + (size_t)ce01 * 128;
            const float* PR10 = g_PR + (size_t)re10 * 128;
            const float* PR11 = g_PR + (size_t)re11 * 128;
            const float* PC10 = g_PC + (size_t)ce10 * 128;
            const float* PC11 = g_PC + (size_t)ce11 * 128;
            #pragma unroll
            for (int nn = 0; nn < 16; nn++) {
                int c = nn * 8 + 2 * ct;
                float2 bb = *(const float2*)&sm[S_EB1 + c];
                {
                    float2 p1 = ldcg2(&PR00[c]);
                    float2 q1 = ldcg2(&PC00[c]);
                    float2 p2 = ldcg2(&PR01[c]);
                    float2 q2 = ldcg2(&PC01[c]);
                    float v0 = acc0[nn][0] + p1.x + q1.x + bb.x;
                    float v1 = acc0[nn][1] + p1.y + q1.y + bb.y;
                    float v2 = acc0[nn][2] + p2.x + q2.x + bb.x;
                    float v3 = acc0[nn][3] + p2.y + q2.y + bb.y;
                    acc0[nn][0] = __uint_as_float(f32_to_tf32(fmaxf(v0, 0.f)));
                    acc0[nn][1] = __uint_as_float(f32_to_tf32(fmaxf(v1, 0.f)));
                    acc0[nn][2] = __uint_as_float(f32_to_tf32(fmaxf(v2, 0.f)));
                    acc0[nn][3] = __uint_as_float(f32_to_tf32(fmaxf(v3, 0.f)));
                }
                {
                    float2 p1 = ldcg2(&PR10[c]);
                    float2 q1 = ldcg2(&PC10[c]);
                    float2 p2 = ldcg2(&PR11[c]);
                    float2 q2 = ldcg2(&PC11[c]);
                    float v0 = acc1[nn][0] + p1.x + q1.x + bb.x;
                    float v1 = acc1[nn][1] + p1.y + q1.y + bb.y;
                    float v2 = acc1[nn][2] + p2.x + q2.x + bb.x;
                    float v3 = acc1[nn][3] + p2.y + q2.y + bb.y;
                    acc1[nn][0] = __uint_as_float(f32_to_tf32(fmaxf(v0, 0.f)));
                    acc1[nn][1] = __uint_as_float(f32_to_tf32(fmaxf(v1, 0.f)));
                    acc1[nn][2] = __uint_as_float(f32_to_tf32(fmaxf(v2, 0.f)));
                    acc1[nn][3] = __uint_as_float(f32_to_tf32(fmaxf(v3, 0.f)));
                }
            }
        }

        // ---- quad-shuffle transpose (both sub-tiles) ----
        #pragma unroll
        for (int kk = 0; kk < 16; kk++) {
            {
                float t0 = __shfl_sync(0xffffffffu, acc0[kk][0], s0, 4);
                float t1 = __shfl_sync(0xffffffffu, acc0[kk][1], s0, 4);
                float t2 = __shfl_sync(0xffffffffu, acc0[kk][2], s0, 4);
                float t3 = __shfl_sync(0xffffffffu, acc0[kk][3], s0, 4);
                float u0 = __shfl_sync(0xffffffffu, acc0[kk][0], s1, 4);
                float u1 = __shfl_sync(0xffffffffu, acc0[kk][1], s1, 4);
                float u2 = __shfl_sync(0xffffffffu, acc0[kk][2], s1, 4);
                float u3 = __shfl_sync(0xffffffffu, acc0[kk][3], s1, 4);
                acc0[kk][0] = sel ? t1 : t0;
                acc0[kk][1] = sel ? t3 : t2;
                acc0[kk][2] = sel ? u1 : u0;
                acc0[kk][3] = sel ? u3 : u2;
            }
            {
                float t0 = __shfl_sync(0xffffffffu, acc1[kk][0], s0, 4);
                float t1 = __shfl_sync(0xffffffffu, acc1[kk][1], s0, 4);
                float t2 = __shfl_sync(0xffffffffu, acc1[kk][2], s0, 4);
                float t3 = __shfl_sync(0xffffffffu, acc1[kk][3], s0, 4);
                float u0 = __shfl_sync(0xffffffffu, acc1[kk][0], s1, 4);
                float u1 = __shfl_sync(0xffffffffu, acc1[kk][1], s1, 4);
                float u2 = __shfl_sync(0xffffffffu, acc1[kk][2], s1, 4);
                float u3 = __shfl_sync(0xffffffffu, acc1[kk][3], s1, 4);
                acc1[kk][0] = sel ? t1 : t0;
                acc1[kk][1] = sel ? t3 : t2;
                acc1[kk][2] = sel ? u1 : u0;
                acc1[kk][3] = sel ? u3 : u2;
            }
        }

        // ---- layer-2 mma: both sub-tiles share every B2 load ----
        float acc20[8][4], acc21[8][4];
        #pragma unroll
        for (int nn = 0; nn < 8; nn++) {
            acc20[nn][0] = acc20[nn][1] = acc20[nn][2] = acc20[nn][3] = 0.f;
            acc21[nn][0] = acc21[nn][1] = acc21[nn][2] = acc21[nn][3] = 0.f;
        }
        #pragma unroll
        for (int kk = 0; kk < 16; kk++) {
            uint32_t a0[4], a1[4];
            a0[0] = __float_as_uint(acc0[kk][0]);
            a0[1] = __float_as_uint(acc0[kk][1]);
            a0[2] = __float_as_uint(acc0[kk][2]);
            a0[3] = __float_as_uint(acc0[kk][3]);
            a1[0] = __float_as_uint(acc1[kk][0]);
            a1[1] = __float_as_uint(acc1[kk][1]);
            a1[2] = __float_as_uint(acc1[kk][2]);
            a1[3] = __float_as_uint(acc1[kk][3]);
            #pragma unroll
            for (int nn = 0; nn < 8; nn++) {
                uint32_t b[2];
                const uint2 bv = *(const uint2*)&smu[S_B2 + (kk * 8 + nn) * 66 + lane * 2];
                b[0] = bv.x; b[1] = bv.y;
                mma_tf32(acc20[nn], a0, b);
                mma_tf32(acc21[nn], a1, b);
            }
        }

        // ---- output: lane-pair exchange -> float4 stores + red.v4 ----
        {
            const int row0 = even ? rA0 : rA0 + 8;
            const int row1 = even ? rA1 : rA1 + 8;
            const int ced0 = even ? ce00 : ce01;
            const int ced1 = even ? ce10 : ce11;
            float* op0 = out_edge + (size_t)(e0 + row0) * 64;
            float* op1 = out_edge + (size_t)(e0 + row1) * 64;
            float* mp0 = g_msg + (size_t)ced0 * 64;
            float* mp1 = g_msg + (size_t)ced1 * 64;
            #pragma unroll
            for (int nn = 0; nn < 8; nn++) {
                int base = nn * 8 + qb;
                float4 bb = *(const float4*)&sm[S_EB2 + base];
                {
                    float sa = __shfl_xor_sync(0xffffffffu, acc20[nn][0], 1);
                    float sb = __shfl_xor_sync(0xffffffffu, acc20[nn][1], 1);
                    float sc = __shfl_xor_sync(0xffffffffu, acc20[nn][2], 1);
                    float sd = __shfl_xor_sync(0xffffffffu, acc20[nn][3], 1);
                    float4 o;
                    if (even) {
                        o = make_float4(acc20[nn][0] + bb.x, acc20[nn][1] + bb.y,
                                        sa + bb.z, sb + bb.w);
                    } else {
                        o = make_float4(sc + bb.x, sd + bb.y,
                                        acc20[nn][2] + bb.z, acc20[nn][3] + bb.w);
                    }
                    *(float4*)(op0 + base) = o;
                    asm volatile("red.global.add.v4.f32 [%0], {%1,%2,%3,%4};"
                                 :: "l"(mp0 + base), "f"(o.x), "f"(o.y), "f"(o.z), "f"(o.w)
                                 : "memory");
                }
                {
                    float sa = __shfl_xor_sync(0xffffffffu, acc21[nn][0], 1);
                    float sb = __shfl_xor_sync(0xffffffffu, acc21[nn][1], 1);
                    float sc = __shfl_xor_sync(0xffffffffu, acc21[nn][2], 1);
                    float sd = __shfl_xor_sync(0xffffffffu, acc21[nn][3], 1);
                    float4 o;
                    if (even) {
                        o = make_float4(acc21[nn][0] + bb.x, acc21[nn][1] + bb.y,
                                        sa + bb.z, sb + bb.w);
                    } else {
                        o = make_float4(sc + bb.x, sd + bb.y,
                                        acc21[nn][2] + bb.z, acc21[nn][3] + bb.w);
                    }
                    *(float4*)(op1 + base) = o;
                    asm volatile("red.global.add.v4.f32 [%0], {%1,%2,%3,%4};"
                                 :: "l"(mp1 + base), "f"(o.x), "f"(o.y), "f"(o.z), "f"(o.w)
                                 : "memory");
                }
            }
        }
    }
}

// ---------------------------------------------------------------------------
// Node kernel — same barrier-free skeleton; A from g_msg (L2-resident),
// PX gather via .cg, no atomics; guarded stores for the OOB tail.
// ---------------------------------------------------------------------------
__global__ void __launch_bounds__(256, 3) node_kernel(
    const float* __restrict__ nW1, const float* __restrict__ nb1,
    const float* __restrict__ nW2, const float* __restrict__ nb2,
    float* __restrict__ out_node)
{
    extern __shared__ float sm[];
    uint32_t* smu = reinterpret_cast<uint32_t*>(sm);

    const int tid  = threadIdx.x;
    const int lane = tid & 31;
    const int w    = tid >> 5;
    const int gr   = lane >> 2;
    const int ct   = lane & 3;
    const int s0   = ct >> 1;
    const int s1   = 2 + (ct >> 1);
    const int sel  = ct & 1;
    const int even = (ct & 1) == 0;
    const int qb   = 4 * (ct >> 1);
    const int rA0  = 32 * w + gr;
    const int rA1  = rA0 + 16;

    // ---- prologue ----
    for (int t = tid; t < 2048; t += 256) {
        int k = t >> 5, n4 = (t & 31) << 2;
        float4 v = *(const float4*)&nW1[(64 + k) * 128 + n4];
        int pane = (k >> 3) * 16 + (n4 >> 3);
        int j    = (k >> 2) & 1;
        int ln0  = ((n4 & 7) << 2) | (k & 3);
        uint32_t* p = &smu[S_B1 + pane * 66 + j];
        p[(ln0 + 0)  * 2] = f32_to_tf32(v.x);
        p[(ln0 + 4)  * 2] = f32_to_tf32(v.y);
        p[(ln0 + 8)  * 2] = f32_to_tf32(v.z);
        p[(ln0 + 12) * 2] = f32_to_tf32(v.w);
    }
    for (int t = tid; t < 2048; t += 256) {
        int k = t >> 4, n4 = (t & 15) << 2;
        float4 v = *(const float4*)&nW2[k * 64 + n4];
        int pane = (k >> 3) * 8 + (n4 >> 3);
        int j    = (k >> 2) & 1;
        int ln0  = ((n4 & 7) << 2) | (k & 3);
        uint32_t* p = &smu[S_B2 + pane * 66 + j];
        p[(ln0 + 0)  * 2] = f32_to_tf32(v.x);
        p[(ln0 + 4)  * 2] = f32_to_tf32(v.y);
        p[(ln0 + 8)  * 2] = f32_to_tf32(v.z);
        p[(ln0 + 12) * 2] = f32_to_tf32(v.w);
    }
    if (tid < 128) sm[S_EB1 + tid] = nb1[tid];
    if (tid < 64)  sm[S_EB2 + tid] = nb2[tid];
    __syncthreads();

    for (int tile = blockIdx.x; tile < NTILE_N; tile += PGRID) {
        const int n0 = tile * 256;
        const int n00 = min(n0 + rA0,      NN - 1);
        const int n01 = min(n0 + rA0 + 8,  NN - 1);
        const int n10 = min(n0 + rA1,      NN - 1);
        const int n11 = min(n0 + rA1 + 8,  NN - 1);

        // layer-1 mma (K=64), A from g_msg (clamped rows; masked at store)
        float acc0[16][4], acc1[16][4];
        #pragma unroll
        for (int nn = 0; nn < 16; nn++) {
            acc0[nn][0] = acc0[nn][1] = acc0[nn][2] = acc0[nn][3] = 0.f;
            acc1[nn][0] = acc1[nn][1] = acc1[nn][2] = acc1[nn][3] = 0.f;
        }
        #pragma unroll
        for (int kk = 0; kk < 8; kk++) {
            const int col = kk * 8 + ct;
            const float* p00 = g_msg + (size_t)n00 * 64 + col;
            const float* p01 = g_msg + (size_t)n01 * 64 + col;
            const float* p10 = g_msg + (size_t)n10 * 64 + col;
            const float* p11 = g_msg + (size_t)n11 * 64 + col;
            uint32_t a0[4], a1[4];
            a0[0] = __float_as_uint(__ldg(p00));
            a0[1] = __float_as_uint(__ldg(p01));
            a0[2] = __float_as_uint(__ldg(p00 + 4));
            a0[3] = __float_as_uint(__ldg(p01 + 4));
            a1[0] = __float_as_uint(__ldg(p10));
            a1[1] = __float_as_uint(__ldg(p11));
            a1[2] = __float_as_uint(__ldg(p10 + 4));
            a1[3] = __float_as_uint(__ldg(p11 + 4));
            #pragma unroll
            for (int nn = 0; nn < 16; nn++) {
                uint32_t b[2];
                const uint2 bv = *(const uint2*)&smu[S_B1 + (kk * 16 + nn) * 66 + lane * 2];
                b[0] = bv.x; b[1] = bv.y;
                mma_tf32(acc0[nn], a0, b);
                mma_tf32(acc1[nn], a1, b);
            }
        }

        // epilogue: H = rna(relu(C1 + PX + nb1))
        {
            const float* PX00 = g_PX + (size_t)n00 * 128;
            const float* PX01 = g_PX + (size_t)n01 * 128;
            const float* PX10 = g_PX + (size_t)n10 * 128;
            const float* PX11 = g_PX + (size_t)n11 * 128;
            #pragma unroll
            for (int nn = 0; nn < 16; nn++) {
                int c = nn * 8 + 2 * ct;
                float2 bb = *(const float2*)&sm[S_EB1 + c];
                {
                    float2 p1 = ldcg2(&PX00[c]);
                    float2 p2 = ldcg2(&PX01[c]);
                    float v0 = acc0[nn][0] + p1.x + bb.x;
                    float v1 = acc0[nn][1] + p1.y + bb.y;
                    float v2 = acc0[nn][2] + p2.x + bb.x;
                    float v3 = acc0[nn][3] + p2.y + bb.y;
                    acc0[nn][0] = __uint_as_float(f32_to_tf32(fmaxf(v0, 0.f)));
                    acc0[nn][1] = __uint_as_float(f32_to_tf32(fmaxf(v1, 0.f)));
                    acc0[nn][2] = __uint_as_float(f32_to_tf32(fmaxf(v2, 0.f)));
                    acc0[nn][3] = __uint_as_float(f32_to_tf32(fmaxf(v3, 0.f)));
                }
                {
                    float2 p1 = ldcg2(&PX10[c]);
                    float2 p2 = ldcg2(&PX11[c]);
                    float v0 = acc1[nn][0] + p1.x + bb.x;
                    float v1 = acc1[nn][1] + p1.y + bb.y;
                    float v2 = acc1[nn][2] + p2.x + bb.x;
                    float v3 = acc1[nn][3] + p2.y + bb.y;
                    acc1[nn][0] = __uint_as_float(f32_to_tf32(fmaxf(v0, 0.f)));
                    acc1[nn][1] = __uint_as_float(f32_to_tf32(fmaxf(v1, 0.f)));
                    acc1[nn][2] = __uint_as_float(f32_to_tf32(fmaxf(v2, 0.f)));
                    acc1[nn][3] = __uint_as_float(f32_to_tf32(fmaxf(v3, 0.f)));
                }
            }
        }

        // quad-shuffle transpose
        #pragma unroll
        for (int kk = 0; kk < 16; kk++) {
            {
                float t0 = __shfl_sync(0xffffffffu, acc0[kk][0], s0, 4);
                float t1 = __shfl_sync(0xffffffffu, acc0[kk][1], s0, 4);
                float t2 = __shfl_sync(0xffffffffu, acc0[kk][2], s0, 4);
                float t3 = __shfl_sync(0xffffffffu, acc0[kk][3], s0, 4);
                float u0 = __shfl_sync(0xffffffffu, acc0[kk][0], s1, 4);
                float u1 = __shfl_sync(0xffffffffu, acc0[kk][1], s1, 4);
                float u2 = __shfl_sync(0xffffffffu, acc0[kk][2], s1, 4);
                float u3 = __shfl_sync(0xffffffffu, acc0[kk][3], s1, 4);
                acc0[kk][0] = sel ? t1 : t0;
                acc0[kk][1] = sel ? t3 : t2;
                acc0[kk][2] = sel ? u1 : u0;
                acc0[kk][3] = sel ? u3 : u2;
            }
            {
                float t0 = __shfl_sync(0xffffffffu, acc1[kk][0], s0, 4);
                float t1 = __shfl_sync(0xffffffffu, acc1[kk][1], s0, 4);
                float t2 = __shfl_sync(0xffffffffu, acc1[kk][2], s0, 4);
                float t3 = __shfl_sync(0xffffffffu, acc1[kk][3], s0, 4);
                float u0 = __shfl_sync(0xffffffffu, acc1[kk][0], s1, 4);
                float u1 = __shfl_sync(0xffffffffu, acc1[kk][1], s1, 4);
                float u2 = __shfl_sync(0xffffffffu, acc1[kk][2], s1, 4);
                float u3 = __shfl_sync(0xffffffffu, acc1[kk][3], s1, 4);
                acc1[kk][0] = sel ? t1 : t0;
                acc1[kk][1] = sel ? t3 : t2;
                acc1[kk][2] = sel ? u1 : u0;
                acc1[kk][3] = sel ? u3 : u2;
            }
        }

        // layer-2 mma (K=128)
        float acc20[8][4], acc21[8][4];
        #pragma unroll
        for (int nn = 0; nn < 8; nn++) {
            acc20[nn][0] = acc20[nn][1] = acc20[nn][2] = acc20[nn][3] = 0.f;
            acc21[nn][0] = acc21[nn][1] = acc21[nn][2] = acc21[nn][3] = 0.f;
        }
        #pragma unroll
        for (int kk = 0; kk < 16; kk++) {
            uint32_t a0[4], a1[4];
            a0[0] = __float_as_uint(acc0[kk][0]);
            a0[1] = __float_as_uint(acc0[kk][1]);
            a0[2] = __float_as_uint(acc0[kk][2]);
            a0[3] = __float_as_uint(acc0[kk][3]);
            a1[0] = __float_as_uint(acc1[kk][0]);
            a1[1] = __float_as_uint(acc1[kk][1]);
            a1[2] = __float_as_uint(acc1[kk][2]);
            a1[3] = __float_as_uint(acc1[kk][3]);
            #pragma unroll
            for (int nn = 0; nn < 8; nn++) {
                uint32_t b[2];
                const uint2 bv = *(const uint2*)&smu[S_B2 + (kk * 8 + nn) * 66 + lane * 2];
                b[0] = bv.x; b[1] = bv.y;
                mma_tf32(acc20[nn], a0, b);
                mma_tf32(acc21[nn], a1, b);
            }
        }

        // output
        {
            const int row0 = even ? rA0 : rA0 + 8;
            const int row1 = even ? rA1 : rA1 + 8;
            const int nd0  = n0 + row0;
            const int nd1  = n0 + row1;
            float* op0 = out_node + (size_t)nd0 * 64;
            float* op1 = out_node + (size_t)nd1 * 64;
            #pragma unroll
            for (int nn = 0; nn < 8; nn++) {
                int base = nn * 8 + qb;
                float4 bb = *(const float4*)&sm[S_EB2 + base];
                {
                    float sa = __shfl_xor_sync(0xffffffffu, acc20[nn][0], 1);
                    float sb = __shfl_xor_sync(0xffffffffu, acc20[nn][1], 1);
                    float sc = __shfl_xor_sync(0xffffffffu, acc20[nn][2], 1);
                    float sd = __shfl_xor_sync(0xffffffffu, acc20[nn][3], 1);
                    float4 o;
                    if (even) {
                        o = make_float4(acc20[nn][0] + bb.x, acc20[nn][1] + bb.y,
                                        sa + bb.z, sb + bb.w);
                    } else {
                        o = make_float4(sc + bb.x, sd + bb.y,
                                        acc20[nn][2] + bb.z, acc20[nn][3] + bb.w);
                    }
                    if (nd0 < NN) *(float4*)(op0 + base) = o;
                }
                {
                    float sa = __shfl_xor_sync(0xffffffffu, acc21[nn][0], 1);
                    float sb = __shfl_xor_sync(0xffffffffu, acc21[nn][1], 1);
                    float sc = __shfl_xor_sync(0xffffffffu, acc21[nn][2], 1);
                    float sd = __shfl_xor_sync(0xffffffffu, acc21[nn][3], 1);
                    float4 o;
                    if (even) {
                        o = make_float4(acc21[nn][0] + bb.x, acc21[nn][1] + bb.y,
                                        sa + bb.z, sb + bb.w);
                    } else {
                        o = make_float4(sc + bb.x, sd + bb.y,
                                        acc21[nn][2] + bb.z, acc21[nn][3] + bb.w);
                    }
                    if (nd1 < NN) *(float4*)(op1 + base) = o;
                }
            }
        }
    }
}

// ---------------------------------------------------------------------------
extern "C" void kernel_launch(void* const* d_in, const int* in_sizes, int n_in,
                              void* d_out, int out_size)
{
    const float* x    = (const float*)d_in[0];
    const int*   ei   = (const int*)  d_in[1];
    const float* ea   = (const float*)d_in[2];
    const float* eW1  = (const float*)d_in[3];
    const float* eb1  = (const float*)d_in[4];
    const float* eW2  = (const float*)d_in[5];
    const float* eb2  = (const float*)d_in[6];
    const float* nW1  = (const float*)d_in[7];
    const float* nb1  = (const float*)d_in[8];
    const float* nW2  = (const float*)d_in[9];
    const float* nb2  = (const float*)d_in[10];

    float* out_node = (float*)d_out;             // [NN, 64]
    float* out_edge = (float*)d_out + NN * ND;   // [NE, 64]

    const int smem_pre = (64 * 68 + 64 * 256) * 4;   // 82944
    const int smem_px  = (64 * 68 + 64 * 128) * 4;   // 50176

    cudaFuncSetAttribute(precompute_kernel,
        cudaFuncAttributeMaxDynamicSharedMemorySize, smem_pre);
    cudaFuncSetAttribute(precompute_px_kernel,
        cudaFuncAttributeMaxDynamicSharedMemorySize, smem_px);
    cudaFuncSetAttribute(edge_kernel,
        cudaFuncAttributeMaxDynamicSharedMemorySize, MMA_SMEM_BYTES);
    cudaFuncSetAttribute(node_kernel,
        cudaFuncAttributeMaxDynamicSharedMemorySize, MMA_SMEM_BYTES);

    zero_msg_kernel<<<(NN * ED / 4) / 256, 256>>>();
    precompute_kernel<<<(NN + 63) / 64, 256, smem_pre>>>(x, eW1);
    precompute_px_kernel<<<(NN + 63) / 64, 256, smem_px>>>(x, nW1);
    edge_kernel<<<PGRID, 256, MMA_SMEM_BYTES>>>(ea, ei, eW1, eb1, eW2, eb2, out_edge);
    node_kernel<<<PGRID, 256, MMA_SMEM_BYTES>>>(nW1, nb1, nW2, nb2, out_node);
}

// round 12
// speedup vs baseline: 3.3475x; 3.3475x over previous
#include <cuda_runtime.h>
#include <cstdint>

// Problem constants
constexpr int NN  = 50000;   // nodes
constexpr int NE  = 800000;  // edges
constexpr int ND  = 64;      // node dim
constexpr int ED  = 64;      // edge dim
constexpr int HID = 128;     // hidden

constexpr int NTILES = NE / 128;            // 6250 edge tiles
constexpr int NTILN  = (NN + 127) / 128;    // 391 node tiles
constexpr int PGRID  = 296;                 // 2 CTAs x 148 SMs, persistent

// Scratch (device globals: allocation-free)
__device__ float g_PR[NN * HID];   // x @ eW1[64:128]   (fp32 exact)
__device__ float g_PC[NN * HID];   // x @ eW1[128:192]  (fp32 exact)
__device__ float g_PX[NN * HID];   // x @ nW1[0:64]     (fp32 exact)
__device__ float g_msg[NN * ED];   // scatter-add accumulator

// ---------------------------------------------------------------------------
// helpers
// ---------------------------------------------------------------------------
__device__ __forceinline__ uint32_t f32_to_tf32(float f) {
    uint32_t u;
    asm("cvt.rna.tf32.f32 %0, %1;" : "=r"(u) : "f"(f));
    return u;
}

__device__ __forceinline__ void mma_tf32(float d[4], const uint32_t a[4],
                                         const uint32_t b[2]) {
    asm volatile(
        "mma.sync.aligned.m16n8k8.row.col.f32.tf32.tf32.f32 "
        "{%0,%1,%2,%3}, {%4,%5,%6,%7}, {%8,%9}, {%0,%1,%2,%3};"
        : "+f"(d[0]), "+f"(d[1]), "+f"(d[2]), "+f"(d[3])
        : "r"(a[0]), "r"(a[1]), "r"(a[2]), "r"(a[3]), "r"(b[0]), "r"(b[1]));
}

__device__ __forceinline__ uint32_t smem_u32(const void* p) {
    uint32_t a;
    asm("{ .reg .u64 t; cvta.to.shared.u64 t, %1; cvt.u32.u64 %0, t; }"
        : "=r"(a) : "l"(p));
    return a;
}

#define CP_ASYNC16(dst_u32, src_ptr) \
    asm volatile("cp.async.cg.shared.global [%0], [%1], 16;" \
                 :: "r"(dst_u32), "l"(src_ptr))
#define CP_ASYNC16_Z(dst_u32, src_ptr, src_bytes) \
    asm volatile("cp.async.cg.shared.global [%0], [%1], 16, %2;" \
                 :: "r"(dst_u32), "l"(src_ptr), "r"(src_bytes))
#define CP_COMMIT()  asm volatile("cp.async.commit_group;")
#define CP_WAIT0()   asm volatile("cp.async.wait_group 0;" ::: "memory")

// ---------------------------------------------------------------------------
__global__ void zero_msg_kernel() {
    int i = blockIdx.x * blockDim.x + threadIdx.x;
    reinterpret_cast<float4*>(g_msg)[i] = make_float4(0.f, 0.f, 0.f, 0.f);
}

// ---------------------------------------------------------------------------
// Precompute PR/PC (fp32 exact): GEMM [NN,64] @ [64,256]
// ---------------------------------------------------------------------------
__global__ void __launch_bounds__(256, 2) precompute_kernel(
    const float* __restrict__ x, const float* __restrict__ eW1)
{
    extern __shared__ float sm[];
    float* Xs = sm;               // [64][68]
    float* Ws = sm + 64 * 68;     // [64][256]

    const int n0 = blockIdx.x * 64;
    const int tid = threadIdx.x;

    for (int idx = tid; idx < 64 * 64; idx += 256) {
        int r = idx >> 6, c = idx & 63;
        int n = n0 + r;
        Xs[r * 68 + c] = (n < NN) ? x[n * 64 + c] : 0.f;
    }
    for (int idx = tid; idx < 64 * 256; idx += 256) {
        int k = idx >> 8, j = idx & 255;
        float v = (j < 128) ? eW1[(64 + k) * 128 + j]
                            : eW1[(128 + k) * 128 + (j - 128)];
        Ws[k * 256 + j] = v;
    }
    __syncthreads();

    const int tx = tid & 15;
    const int ty = tid >> 4;

    float acc[4][16];
    #pragma unroll
    for (int i = 0; i < 4; i++)
        #pragma unroll
        for (int j = 0; j < 16; j++) acc[i][j] = 0.f;

    #pragma unroll 4
    for (int k = 0; k < 64; k++) {
        float a[4];
        #pragma unroll
        for (int i = 0; i < 4; i++) a[i] = Xs[(ty * 4 + i) * 68 + k];
        const float4 b0 = *(const float4*)&Ws[k * 256 + tx * 16 + 0];
        const float4 b1 = *(const float4*)&Ws[k * 256 + tx * 16 + 4];
        const float4 b2 = *(const float4*)&Ws[k * 256 + tx * 16 + 8];
        const float4 b3 = *(const float4*)&Ws[k * 256 + tx * 16 + 12];
        float b[16] = {b0.x, b0.y, b0.z, b0.w, b1.x, b1.y, b1.z, b1.w,
                       b2.x, b2.y, b2.z, b2.w, b3.x, b3.y, b3.z, b3.w};
        #pragma unroll
        for (int i = 0; i < 4; i++)
            #pragma unroll
            for (int j = 0; j < 16; j++)
                acc[i][j] = fmaf(a[i], b[j], acc[i][j]);
    }

    float* dst = (tx < 8) ? g_PR : g_PC;
    int    cb  = (tx < 8) ? tx * 16 : (tx - 8) * 16;
    #pragma unroll
    for (int i = 0; i < 4; i++) {
        int n = n0 + ty * 4 + i;
        if (n >= NN) continue;
        #pragma unroll
        for (int j = 0; j < 16; j += 4) {
            float4 o = make_float4(acc[i][j], acc[i][j + 1],
                                   acc[i][j + 2], acc[i][j + 3]);
            *(float4*)&dst[n * 128 + cb + j] = o;
        }
    }
}

// ---------------------------------------------------------------------------
// Precompute PX (fp32 exact): PX = x @ nW1[0:64]   [NN,128]
// ---------------------------------------------------------------------------
__global__ void __launch_bounds__(256, 2) precompute_px_kernel(
    const float* __restrict__ x, const float* __restrict__ nW1)
{
    extern __shared__ float sm[];
    float* Xs = sm;               // [64][68]
    float* Ws = sm + 64 * 68;     // [64][128]

    const int n0 = blockIdx.x * 64;
    const int tid = threadIdx.x;

    for (int idx = tid; idx < 64 * 64; idx += 256) {
        int r = idx >> 6, c = idx & 63;
        int n = n0 + r;
        Xs[r * 68 + c] = (n < NN) ? x[n * 64 + c] : 0.f;
    }
    for (int idx = tid; idx < 64 * 128; idx += 256)
        Ws[idx] = nW1[idx];
    __syncthreads();

    const int tx = tid & 15;
    const int ty = tid >> 4;

    float acc[4][8];
    #pragma unroll
    for (int i = 0; i < 4; i++)
        #pragma unroll
        for (int j = 0; j < 8; j++) acc[i][j] = 0.f;

    #pragma unroll 4
    for (int k = 0; k < 64; k++) {
        float a[4];
        #pragma unroll
        for (int i = 0; i < 4; i++) a[i] = Xs[(ty * 4 + i) * 68 + k];
        const float4 b0 = *(const float4*)&Ws[k * 128 + tx * 8 + 0];
        const float4 b1 = *(const float4*)&Ws[k * 128 + tx * 8 + 4];
        float b[8] = {b0.x, b0.y, b0.z, b0.w, b1.x, b1.y, b1.z, b1.w};
        #pragma unroll
        for (int i = 0; i < 4; i++)
            #pragma unroll
            for (int j = 0; j < 8; j++)
                acc[i][j] = fmaf(a[i], b[j], acc[i][j]);
    }

    #pragma unroll
    for (int i = 0; i < 4; i++) {
        int n = n0 + ty * 4 + i;
        if (n >= NN) continue;
        *(float4*)&g_PX[n * 128 + tx * 8 + 0] =
            make_float4(acc[i][0], acc[i][1], acc[i][2], acc[i][3]);
        *(float4*)&g_PX[n * 128 + tx * 8 + 4] =
            make_float4(acc[i][4], acc[i][5], acc[i][6], acc[i][7]);
    }
}

// ---------------------------------------------------------------------------
// Smem layout for persistent mma kernels (103168 B, 2 CTAs/SM)
// A slabs are WARP-PRIVATE (warp w owns rows [16w,16w+16)) -> no block
// barriers in the main loop; only __syncwarp around each warp's cp.async.
// ---------------------------------------------------------------------------
constexpr int S_A   = 0;          // A [128][68] row-major (raw fp32)
constexpr int S_B1  = 8704;       // B1frag [pane=kk*16+nn][66]
constexpr int S_B2  = 17152;      // B2frag [pane=kk*8+nn][66]
constexpr int S_EB1 = 25600;      // bias1 [128]
constexpr int S_EB2 = 25728;      // bias2 [64]
constexpr int MMA_SMEM_BYTES = 25792 * 4;   // 103168

// ---------------------------------------------------------------------------
// Edge kernel — persistent, barrier-free main loop, per-warp A slabs.
// 256 threads / 8 warps; 128-edge tiles; warp w owns rows [16w, 16w+16).
// ---------------------------------------------------------------------------
__global__ void __launch_bounds__(256, 2) edge_kernel(
    const float* __restrict__ edge_attr,
    const int*   __restrict__ edge_index,   // [2][NE]
    const float* __restrict__ eW1,
    const float* __restrict__ eb1,
    const float* __restrict__ eW2,
    const float* __restrict__ eb2,
    float* __restrict__ out_edge)
{
    extern __shared__ float sm[];
    uint32_t* smu = reinterpret_cast<uint32_t*>(sm);
    const uint32_t sbase = smem_u32(sm);

    const int tid  = threadIdx.x;
    const int lane = tid & 31;
    const int w    = tid >> 5;
    const int gr   = lane >> 2;
    const int ct   = lane & 3;
    const int s0   = ct >> 1;
    const int s1   = 2 + (ct >> 1);
    const int sel  = ct & 1;
    const int even = (ct & 1) == 0;
    const int qb   = 4 * (ct >> 1);
    const int r1   = 16 * w + gr;
    const int r2   = r1 + 8;

    // per-warp A slab fill: 16 rows x 64 cols, 8 float4 per lane
    // lane t covers (t + 32*i): row_local = idx>>4, c4 = (idx&15)*4
    const uint32_t slabBase = sbase + (S_A + 16 * w * 68) * 4;

    // ---- prologue: B fragments + biases (block-cooperative, once) ----
    for (int t = tid; t < 2048; t += 256) {
        int k = t >> 5, n4 = (t & 31) << 2;
        float4 v = *(const float4*)&eW1[k * 128 + n4];
        int pane = (k >> 3) * 16 + (n4 >> 3);
        int j    = (k >> 2) & 1;
        int ln0  = ((n4 & 7) << 2) | (k & 3);
        uint32_t* p = &smu[S_B1 + pane * 66 + j];
        p[(ln0 + 0)  * 2] = f32_to_tf32(v.x);
        p[(ln0 + 4)  * 2] = f32_to_tf32(v.y);
        p[(ln0 + 8)  * 2] = f32_to_tf32(v.z);
        p[(ln0 + 12) * 2] = f32_to_tf32(v.w);
    }
    for (int t = tid; t < 2048; t += 256) {
        int k = t >> 4, n4 = (t & 15) << 2;
        float4 v = *(const float4*)&eW2[k * 64 + n4];
        int pane = (k >> 3) * 8 + (n4 >> 3);
        int j    = (k >> 2) & 1;
        int ln0  = ((n4 & 7) << 2) | (k & 3);
        uint32_t* p = &smu[S_B2 + pane * 66 + j];
        p[(ln0 + 0)  * 2] = f32_to_tf32(v.x);
        p[(ln0 + 4)  * 2] = f32_to_tf32(v.y);
        p[(ln0 + 8)  * 2] = f32_to_tf32(v.z);
        p[(ln0 + 12) * 2] = f32_to_tf32(v.w);
    }
    if (tid < 128) sm[S_EB1 + tid] = eb1[tid];
    if (tid < 64)  sm[S_EB2 + tid] = eb2[tid];

    // ---- per-warp A slab for first tile ----
    {
        int e0 = blockIdx.x * 128;
        #pragma unroll
        for (int i = 0; i < 8; i++) {
            int idx = lane + 32 * i;
            int rl = idx >> 4, c4 = (idx & 15) << 2;
            CP_ASYNC16(slabBase + (rl * 68 + c4) * 4,
                       edge_attr + (size_t)(e0 + 16 * w + rl) * 64 + c4);
        }
        CP_COMMIT();
    }
    __syncthreads();   // B fragments visible; the ONLY block barrier
    CP_WAIT0();
    __syncwarp();

    // ---- persistent tile loop (no block barriers) ----
    for (int tile = blockIdx.x; tile < NTILES; tile += PGRID) {
        const int e0 = tile * 128;

        const int re1 = __ldg(&edge_index[e0 + r1]);
        const int re2 = __ldg(&edge_index[e0 + r2]);
        const int ce1 = __ldg(&edge_index[NE + e0 + r1]);
        const int ce2 = __ldg(&edge_index[NE + e0 + r2]);

        // layer-1 mma (A from own slab, conflict-free scalar LDS)
        float acc[16][4];
        #pragma unroll
        for (int nn = 0; nn < 16; nn++) {
            acc[nn][0] = acc[nn][1] = acc[nn][2] = acc[nn][3] = 0.f;
        }
        #pragma unroll
        for (int kk = 0; kk < 8; kk++) {
            const int col = kk * 8 + ct;
            uint32_t a[4];
            a[0] = smu[S_A + r1 * 68 + col];
            a[1] = smu[S_A + r2 * 68 + col];
            a[2] = smu[S_A + r1 * 68 + col + 4];
            a[3] = smu[S_A + r2 * 68 + col + 4];
            #pragma unroll
            for (int nn = 0; nn < 16; nn++) {
                uint32_t b[2];
                const uint2 bv = *(const uint2*)&smu[S_B1 + (kk * 16 + nn) * 66 + lane * 2];
                b[0] = bv.x; b[1] = bv.y;
                mma_tf32(acc[nn], a, b);
            }
        }
        __syncwarp();   // all lanes done reading this warp's slab

        // per-warp prefetch of next tile's slab (hidden by epilogue + L2 mma)
        {
            int ntile = tile + PGRID;
            if (ntile < NTILES) {
                int ne0 = ntile * 128;
                #pragma unroll
                for (int i = 0; i < 8; i++) {
                    int idx = lane + 32 * i;
                    int rl = idx >> 4, c4 = (idx & 15) << 2;
                    CP_ASYNC16(slabBase + (rl * 68 + c4) * 4,
                               edge_attr + (size_t)(ne0 + 16 * w + rl) * 64 + c4);
                }
            }
            CP_COMMIT();
        }

        // epilogue: H = rna(relu(C1 + PR + PC + eb1)), plain (L1-cached) gathers
        {
            const float* PR1 = g_PR + (size_t)re1 * 128;
            const float* PR2 = g_PR + (size_t)re2 * 128;
            const float* PC1 = g_PC + (size_t)ce1 * 128;
            const float* PC2 = g_PC + (size_t)ce2 * 128;
            #pragma unroll
            for (int nn = 0; nn < 16; nn++) {
                int c = nn * 8 + 2 * ct;
                float2 p1 = *(const float2*)&PR1[c];
                float2 q1 = *(const float2*)&PC1[c];
                float2 p2 = *(const float2*)&PR2[c];
                float2 q2 = *(const float2*)&PC2[c];
                float2 bb = *(const float2*)&sm[S_EB1 + c];
                float v0 = acc[nn][0] + p1.x + q1.x + bb.x;
                float v1 = acc[nn][1] + p1.y + q1.y + bb.y;
                float v2 = acc[nn][2] + p2.x + q2.x + bb.x;
                float v3 = acc[nn][3] + p2.y + q2.y + bb.y;
                acc[nn][0] = __uint_as_float(f32_to_tf32(fmaxf(v0, 0.f)));
                acc[nn][1] = __uint_as_float(f32_to_tf32(fmaxf(v1, 0.f)));
                acc[nn][2] = __uint_as_float(f32_to_tf32(fmaxf(v2, 0.f)));
                acc[nn][3] = __uint_as_float(f32_to_tf32(fmaxf(v3, 0.f)));
            }
        }

        // quad-shuffle transpose -> layer-2 A fragments
        #pragma unroll
        for (int kk = 0; kk < 16; kk++) {
            float t0 = __shfl_sync(0xffffffffu, acc[kk][0], s0, 4);
            float t1 = __shfl_sync(0xffffffffu, acc[kk][1], s0, 4);
            float t2 = __shfl_sync(0xffffffffu, acc[kk][2], s0, 4);
            float t3 = __shfl_sync(0xffffffffu, acc[kk][3], s0, 4);
            float u0 = __shfl_sync(0xffffffffu, acc[kk][0], s1, 4);
            float u1 = __shfl_sync(0xffffffffu, acc[kk][1], s1, 4);
            float u2 = __shfl_sync(0xffffffffu, acc[kk][2], s1, 4);
            float u3 = __shfl_sync(0xffffffffu, acc[kk][3], s1, 4);
            acc[kk][0] = sel ? t1 : t0;
            acc[kk][1] = sel ? t3 : t2;
            acc[kk][2] = sel ? u1 : u0;
            acc[kk][3] = sel ? u3 : u2;
        }

        // layer-2 mma
        float acc2[8][4];
        #pragma unroll
        for (int nn = 0; nn < 8; nn++) {
            acc2[nn][0] = acc2[nn][1] = acc2[nn][2] = acc2[nn][3] = 0.f;
        }
        #pragma unroll
        for (int kk = 0; kk < 16; kk++) {
            uint32_t a[4];
            a[0] = __float_as_uint(acc[kk][0]);
            a[1] = __float_as_uint(acc[kk][1]);
            a[2] = __float_as_uint(acc[kk][2]);
            a[3] = __float_as_uint(acc[kk][3]);
            #pragma unroll
            for (int nn = 0; nn < 8; nn++) {
                uint32_t b[2];
                const uint2 bv = *(const uint2*)&smu[S_B2 + (kk * 8 + nn) * 66 + lane * 2];
                b[0] = bv.x; b[1] = bv.y;
                mma_tf32(acc2[nn], a, b);
            }
        }

        // output: lane-pair exchange -> float4 stores + red.v4
        {
            const int row  = even ? r1 : r2;
            const int ced  = even ? ce1 : ce2;
            float* op = out_edge + (size_t)(e0 + row) * 64;
            float* mp = g_msg + (size_t)ced * 64;
            #pragma unroll
            for (int nn = 0; nn < 8; nn++) {
                float sa = __shfl_xor_sync(0xffffffffu, acc2[nn][0], 1);
                float sb = __shfl_xor_sync(0xffffffffu, acc2[nn][1], 1);
                float sc = __shfl_xor_sync(0xffffffffu, acc2[nn][2], 1);
                float sd = __shfl_xor_sync(0xffffffffu, acc2[nn][3], 1);
                int base = nn * 8 + qb;
                float4 bb = *(const float4*)&sm[S_EB2 + base];
                float4 o;
                if (even) {
                    o = make_float4(acc2[nn][0] + bb.x, acc2[nn][1] + bb.y,
                                    sa + bb.z, sb + bb.w);
                } else {
                    o = make_float4(sc + bb.x, sd + bb.y,
                                    acc2[nn][2] + bb.z, acc2[nn][3] + bb.w);
                }
                *(float4*)(op + base) = o;
                asm volatile("red.global.add.v4.f32 [%0], {%1,%2,%3,%4};"
                             :: "l"(mp + base), "f"(o.x), "f"(o.y), "f"(o.z), "f"(o.w)
                             : "memory");
            }
        }

        // wait for this warp's prefetched slab before next iteration
        CP_WAIT0();
        __syncwarp();
    }
}

// ---------------------------------------------------------------------------
// Node kernel — same barrier-free per-warp-slab skeleton; no atomics.
// ---------------------------------------------------------------------------
__global__ void __launch_bounds__(256, 2) node_kernel(
    const float* __restrict__ nW1, const float* __restrict__ nb1,
    const float* __restrict__ nW2, const float* __restrict__ nb2,
    float* __restrict__ out_node)
{
    extern __shared__ float sm[];
    uint32_t* smu = reinterpret_cast<uint32_t*>(sm);
    const uint32_t sbase = smem_u32(sm);

    const int tid  = threadIdx.x;
    const int lane = tid & 31;
    const int w    = tid >> 5;
    const int gr   = lane >> 2;
    const int ct   = lane & 3;
    const int s0   = ct >> 1;
    const int s1   = 2 + (ct >> 1);
    const int sel  = ct & 1;
    const int even = (ct & 1) == 0;
    const int qb   = 4 * (ct >> 1);
    const int r1   = 16 * w + gr;
    const int r2   = r1 + 8;

    const uint32_t slabBase = sbase + (S_A + 16 * w * 68) * 4;

    // ---- prologue ----
    for (int t = tid; t < 2048; t += 256) {
        int k = t >> 5, n4 = (t & 31) << 2;
        float4 v = *(const float4*)&nW1[(64 + k) * 128 + n4];
        int pane = (k >> 3) * 16 + (n4 >> 3);
        int j    = (k >> 2) & 1;
        int ln0  = ((n4 & 7) << 2) | (k & 3);
        uint32_t* p = &smu[S_B1 + pane * 66 + j];
        p[(ln0 + 0)  * 2] = f32_to_tf32(v.x);
        p[(ln0 + 4)  * 2] = f32_to_tf32(v.y);
        p[(ln0 + 8)  * 2] = f32_to_tf32(v.z);
        p[(ln0 + 12) * 2] = f32_to_tf32(v.w);
    }
    for (int t = tid; t < 2048; t += 256) {
        int k = t >> 4, n4 = (t & 15) << 2;
        float4 v = *(const float4*)&nW2[k * 64 + n4];
        int pane = (k >> 3) * 8 + (n4 >> 3);
        int j    = (k >> 2) & 1;
        int ln0  = ((n4 & 7) << 2) | (k & 3);
        uint32_t* p = &smu[S_B2 + pane * 66 + j];
        p[(ln0 + 0)  * 2] = f32_to_tf32(v.x);
        p[(ln0 + 4)  * 2] = f32_to_tf32(v.y);
        p[(ln0 + 8)  * 2] = f32_to_tf32(v.z);
        p[(ln0 + 12) * 2] = f32_to_tf32(v.w);
    }
    if (tid < 128) sm[S_EB1 + tid] = nb1[tid];
    if (tid < 64)  sm[S_EB2 + tid] = nb2[tid];

    {
        int n0 = blockIdx.x * 128;
        #pragma unroll
        for (int i = 0; i < 8; i++) {
            int idx = lane + 32 * i;
            int rl = idx >> 4, c4 = (idx & 15) << 2;
            int row = n0 + 16 * w + rl;
            uint32_t nbytes = (row < NN) ? 16u : 0u;
            const float* src = g_msg + (size_t)min(row, NN - 1) * 64 + c4;
            CP_ASYNC16_Z(slabBase + (rl * 68 + c4) * 4, src, nbytes);
        }
        CP_COMMIT();
    }
    __syncthreads();
    CP_WAIT0();
    __syncwarp();

    for (int tile = blockIdx.x; tile < NTILN; tile += PGRID) {
        const int n0 = tile * 128;

        float acc[16][4];
        #pragma unroll
        for (int nn = 0; nn < 16; nn++) {
            acc[nn][0] = acc[nn][1] = acc[nn][2] = acc[nn][3] = 0.f;
        }
        #pragma unroll
        for (int kk = 0; kk < 8; kk++) {
            const int col = kk * 8 + ct;
            uint32_t a[4];
            a[0] = smu[S_A + r1 * 68 + col];
            a[1] = smu[S_A + r2 * 68 + col];
            a[2] = smu[S_A + r1 * 68 + col + 4];
            a[3] = smu[S_A + r2 * 68 + col + 4];
            #pragma unroll
            for (int nn = 0; nn < 16; nn++) {
                uint32_t b[2];
                const uint2 bv = *(const uint2*)&smu[S_B1 + (kk * 16 + nn) * 66 + lane * 2];
                b[0] = bv.x; b[1] = bv.y;
                mma_tf32(acc[nn], a, b);
            }
        }
        __syncwarp();

        {
            int ntile = tile + PGRID;
            if (ntile < NTILN) {
                int nn0 = ntile * 128;
                #pragma unroll
                for (int i = 0; i < 8; i++) {
                    int idx = lane + 32 * i;
                    int rl = idx >> 4, c4 = (idx & 15) << 2;
                    int row = nn0 + 16 * w + rl;
                    uint32_t nbytes = (row < NN) ? 16u : 0u;
                    const float* src = g_msg + (size_t)min(row, NN - 1) * 64 + c4;
                    CP_ASYNC16_Z(slabBase + (rl * 68 + c4) * 4, src, nbytes);
                }
            }
            CP_COMMIT();
        }

        {
            const float* PX1 = g_PX + (size_t)min(n0 + r1, NN - 1) * 128;
            const float* PX2 = g_PX + (size_t)min(n0 + r2, NN - 1) * 128;
            #pragma unroll
            for (int nn = 0; nn < 16; nn++) {
                int c = nn * 8 + 2 * ct;
                float2 p1 = *(const float2*)&PX1[c];
                float2 p2 = *(const float2*)&PX2[c];
                float2 bb = *(const float2*)&sm[S_EB1 + c];
                float v0 = acc[nn][0] + p1.x + bb.x;
                float v1 = acc[nn][1] + p1.y + bb.y;
                float v2 = acc[nn][2] + p2.x + bb.x;
                float v3 = acc[nn][3] + p2.y + bb.y;
                acc[nn][0] = __uint_as_float(f32_to_tf32(fmaxf(v0, 0.f)));
                acc[nn][1] = __uint_as_float(f32_to_tf32(fmaxf(v1, 0.f)));
                acc[nn][2] = __uint_as_float(f32_to_tf32(fmaxf(v2, 0.f)));
                acc[nn][3] = __uint_as_float(f32_to_tf32(fmaxf(v3, 0.f)));
            }
        }

        #pragma unroll
        for (int kk = 0; kk < 16; kk++) {
            float t0 = __shfl_sync(0xffffffffu, acc[kk][0], s0, 4);
            float t1 = __shfl_sync(0xffffffffu, acc[kk][1], s0, 4);
            float t2 = __shfl_sync(0xffffffffu, acc[kk][2], s0, 4);
            float t3 = __shfl_sync(0xffffffffu, acc[kk][3], s0, 4);
            float u0 = __shfl_sync(0xffffffffu, acc[kk][0], s1, 4);
            float u1 = __shfl_sync(0xffffffffu, acc[kk][1], s1, 4);
            float u2 = __shfl_sync(0xffffffffu, acc[kk][2], s1, 4);
            float u3 = __shfl_sync(0xffffffffu, acc[kk][3], s1, 4);
            acc[kk][0] = sel ? t1 : t0;
            acc[kk][1] = sel ? t3 : t2;
            acc[kk][2] = sel ? u1 : u0;
            acc[kk][3] = sel ? u3 : u2;
        }

        float acc2[8][4];
        #pragma unroll
        for (int nn = 0; nn < 8; nn++) {
            acc2[nn][0] = acc2[nn][1] = acc2[nn][2] = acc2[nn][3] = 0.f;
        }
        #pragma unroll
        for (int kk = 0; kk < 16; kk++) {
            uint32_t a[4];
            a[0] = __float_as_uint(acc[kk][0]);
            a[1] = __float_as_uint(acc[kk][1]);
            a[2] = __float_as_uint(acc[kk][2]);
            a[3] = __float_as_uint(acc[kk][3]);
            #pragma unroll
            for (int nn = 0; nn < 8; nn++) {
                uint32_t b[2];
                const uint2 bv = *(const uint2*)&smu[S_B2 + (kk * 8 + nn) * 66 + lane * 2];
                b[0] = bv.x; b[1] = bv.y;
                mma_tf32(acc2[nn], a, b);
            }
        }

        {
            const int row = even ? r1 : r2;
            const int n   = n0 + row;
            float* op = out_node + (size_t)n * 64;
            #pragma unroll
            for (int nn = 0; nn < 8; nn++) {
                float sa = __shfl_xor_sync(0xffffffffu, acc2[nn][0], 1);
                float sb = __shfl_xor_sync(0xffffffffu, acc2[nn][1], 1);
                float sc = __shfl_xor_sync(0xffffffffu, acc2[nn][2], 1);
                float sd = __shfl_xor_sync(0xffffffffu, acc2[nn][3], 1);
                int base = nn * 8 + qb;
                float4 bb = *(const float4*)&sm[S_EB2 + base];
                float4 o;
                if (even) {
                    o = make_float4(acc2[nn][0] + bb.x, acc2[nn][1] + bb.y,
                                    sa + bb.z, sb + bb.w);
                } else {
                    o = make_float4(sc + bb.x, sd + bb.y,
                                    acc2[nn][2] + bb.z, acc2[nn][3] + bb.w);
                }
                if (n < NN) *(float4*)(op + base) = o;
            }
        }

        CP_WAIT0();
        __syncwarp();
    }
}

// ---------------------------------------------------------------------------
extern "C" void kernel_launch(void* const* d_in, const int* in_sizes, int n_in,
                              void* d_out, int out_size)
{
    const float* x    = (const float*)d_in[0];
    const int*   ei   = (const int*)  d_in[1];
    const float* ea   = (const float*)d_in[2];
    const float* eW1  = (const float*)d_in[3];
    const float* eb1  = (const float*)d_in[4];
    const float* eW2  = (const float*)d_in[5];
    const float* eb2  = (const float*)d_in[6];
    const float* nW1  = (const float*)d_in[7];
    const float* nb1  = (const float*)d_in[8];
    const float* nW2  = (const float*)d_in[9];
    const float* nb2  = (const float*)d_in[10];

    float* out_node = (float*)d_out;             // [NN, 64]
    float* out_edge = (float*)d_out + NN * ND;   // [NE, 64]

    const int smem_pre = (64 * 68 + 64 * 256) * 4;   // 82944
    const int smem_px  = (64 * 68 + 64 * 128) * 4;   // 50176

    cudaFuncSetAttribute(precompute_kernel,
        cudaFuncAttributeMaxDynamicSharedMemorySize, smem_pre);
    cudaFuncSetAttribute(precompute_px_kernel,
        cudaFuncAttributeMaxDynamicSharedMemorySize, smem_px);
    cudaFuncSetAttribute(edge_kernel,
        cudaFuncAttributeMaxDynamicSharedMemorySize, MMA_SMEM_BYTES);
    cudaFuncSetAttribute(node_kernel,
        cudaFuncAttributeMaxDynamicSharedMemorySize, MMA_SMEM_BYTES);

    zero_msg_kernel<<<(NN * ED / 4) / 256, 256>>>();
    precompute_kernel<<<(NN + 63) / 64, 256, smem_pre>>>(x, eW1);
    precompute_px_kernel<<<(NN + 63) / 64, 256, smem_px>>>(x, nW1);
    edge_kernel<<<PGRID, 256, MMA_SMEM_BYTES>>>(ea, ei, eW1, eb1, eW2, eb2, out_edge);
    node_kernel<<<PGRID, 256, MMA_SMEM_BYTES>>>(nW1, nb1, nW2, nb2, out_node);
}